// round 17
// baseline (speedup 1.0000x reference)
#include <cuda_runtime.h>
#include <cuda_bf16.h>
#include <math.h>

// Problem dims: H=256, B=64, L=128, LABEL=128
// s = t*64 + b, S = 8192 sequential cells.

#define NSTEPS 8192
#define CHAIN_CTAS 16             // one 16-CTA cluster (non-portable size)
#define RHELP_BLOCKS 64           // out_prev matvec helpers (resident early)
#define GEMM_BLOCKS 2048
#define FC_BLOCKS   1024
#define MAIL_DEPTH 67
#define MAIL_SLOT 144             // u64 words/slot: 16 groups * 9 (8 pairs + 1 pad)

// Scratch (device globals: allocation-free rule)
__device__ float    g_G[8192u * 1024u];  // 32 MB: input-gate GEMM + bias
__device__ unsigned g_R[8192u * 1024u];  // 32 MB: stamped W_r·h[s-64] contributions
__device__ unsigned g_Hs[8192u * 256u];  // 8 MB: stamped h mirror (fc + helpers)
__device__ unsigned g_gdone[128];        // per-M-tile completion counters

// ---------------------------------------------------------------------------
// helpers
// ---------------------------------------------------------------------------
__device__ __forceinline__ unsigned ld_acq32(const unsigned* p) {
    unsigned v;
    asm volatile("ld.acquire.gpu.global.b32 %0, [%1];" : "=r"(v) : "l"(p) : "memory");
    return v;
}
__device__ __forceinline__ unsigned long long pk2(float lo, float hi) {
    unsigned long long r;
    asm("mov.b64 %0, {%1, %2};" : "=l"(r) : "f"(lo), "f"(hi));
    return r;
}
__device__ __forceinline__ void upk2(unsigned long long v, float& lo, float& hi) {
    asm("mov.b64 {%0, %1}, %2;" : "=f"(lo), "=f"(hi) : "l"(v));
}
__device__ __forceinline__ unsigned long long ffma2(
    unsigned long long a, unsigned long long b, unsigned long long c) {
    unsigned long long d;
    asm("fma.rn.f32x2 %0, %1, %2, %3;" : "=l"(d) : "l"(a), "l"(b), "l"(c));
    return d;
}
__device__ __forceinline__ unsigned smem_u32(const void* p) {
    unsigned a;
    asm("{ .reg .u64 t; cvta.to.shared.u64 t, %1; cvt.u32.u64 %0, t; }"
        : "=r"(a) : "l"(p));
    return a;
}
__device__ __forceinline__ unsigned mapa_rank(unsigned laddr, unsigned rank) {
    unsigned r;
    asm("mapa.shared::cluster.u32 %0, %1, %2;" : "=r"(r) : "r"(laddr), "r"(rank));
    return r;
}
__device__ __forceinline__ void st_clu32(unsigned addr, unsigned v) {
    asm volatile("st.relaxed.cluster.shared::cluster.b32 [%0], %1;"
                 :: "r"(addr), "r"(v) : "memory");
}
__device__ __forceinline__ unsigned long long ld_clu64(unsigned addr) {
    unsigned long long v;
    asm volatile("ld.relaxed.cluster.shared.b64 %0, [%1];" : "=l"(v) : "r"(addr) : "memory");
    return v;
}
// stamped global words: relaxed 32-bit store/load (morally strong pair)
__device__ __forceinline__ void st_rlx32g(unsigned* p, unsigned v) {
    asm volatile("st.relaxed.gpu.global.b32 [%0], %1;" :: "l"(p), "r"(v) : "memory");
}
__device__ __forceinline__ unsigned ld_rlx32g(const unsigned* p) {
    unsigned v;
    asm volatile("ld.relaxed.gpu.global.b32 %0, [%1];" : "=r"(v) : "l"(p) : "memory");
    return v;
}
__device__ __forceinline__ float fast_sigmoid(float x) {
    return __fdividef(1.f, 1.f + __expf(-x));
}
__device__ __forceinline__ float fast_tanh(float x) {
    return 1.f - __fdividef(2.f, __expf(2.f * x) + 1.f);
}

// ---------------------------------------------------------------------------
// GEMM body (proven tile code): G[s][j] = feats[s].W_ih[j][0:1024] + bias[j]
// ---------------------------------------------------------------------------
__device__ void gemm_body(
    float* smem, int gb,
    const float* __restrict__ x, const float* __restrict__ hi,
    const float* __restrict__ W_ih,
    const float* __restrict__ b_ih, const float* __restrict__ b_hh)
{
    float (*As)[68] = (float(*)[68])smem;
    float (*Bs)[68] = (float(*)[68])(smem + 16 * 68);

    const int tid = threadIdx.x;
    const int bn  = gb & 15;
    const int bm  = gb >> 4;           // M tiles complete in s-order
    const int tx  = tid & 15;
    const int ty  = tid >> 4;

    const int lm  = tid >> 2;
    const int lk4 = (tid & 3) * 4;

    const int s  = bm * 64 + lm;
    const int t  = s >> 6, b = s & 63;
    const float* xrow  = &x [((size_t)(b * 128 + t)) << 9];
    const float* hirow = &hi[((size_t)(b * 128 + t)) << 9];
    const float* wrow  = &W_ih[(size_t)(bn * 64 + (tid >> 2)) * 1280];

    float acc[4][4] = {};

    for (int kt = 0; kt < 64; kt++) {
        const int kbase = kt * 16 + lk4;
        float4 av;
        if (kbase < 512) av = *(const float4*)&xrow[kbase];
        else             av = *(const float4*)&hirow[kbase - 512];
        As[lk4 + 0][lm] = av.x;
        As[lk4 + 1][lm] = av.y;
        As[lk4 + 2][lm] = av.z;
        As[lk4 + 3][lm] = av.w;
        float4 bv = *(const float4*)&wrow[kbase];
        Bs[lk4 + 0][tid >> 2] = bv.x;
        Bs[lk4 + 1][tid >> 2] = bv.y;
        Bs[lk4 + 2][tid >> 2] = bv.z;
        Bs[lk4 + 3][tid >> 2] = bv.w;
        __syncthreads();

#pragma unroll
        for (int kk = 0; kk < 16; kk++) {
            float ar[4], br[4];
#pragma unroll
            for (int i = 0; i < 4; i++) ar[i] = As[kk][ty * 4 + i];
#pragma unroll
            for (int j = 0; j < 4; j++) br[j] = Bs[kk][tx * 4 + j];
#pragma unroll
            for (int i = 0; i < 4; i++)
#pragma unroll
                for (int j = 0; j < 4; j++)
                    acc[i][j] = fmaf(ar[i], br[j], acc[i][j]);
        }
        __syncthreads();
    }

    const int col0 = bn * 64 + tx * 4;
    float bias[4];
#pragma unroll
    for (int j = 0; j < 4; j++) bias[j] = b_ih[col0 + j] + b_hh[col0 + j];
#pragma unroll
    for (int i = 0; i < 4; i++) {
        const size_t row = (size_t)(bm * 64 + ty * 4 + i);
        float4 v;
        v.x = acc[i][0] + bias[0];
        v.y = acc[i][1] + bias[1];
        v.z = acc[i][2] + bias[2];
        v.w = acc[i][3] + bias[3];
        *(float4*)&g_G[row * 1024 + col0] = v;
    }

    __threadfence();
    __syncthreads();
    if (tid == 0) atomicAdd(&g_gdone[bm], 1u);
}

// ---------------------------------------------------------------------------
// R-helper body: block hb (0..63) owns gate rows j = 16*hb .. 16*hb+15 with
// W_r weights register-resident (16 f32/thread). For each s in [64, NSTEPS):
// poll stamped h[s-64] words from g_Hs (per-word validation), stage into a
// double-buffered smem row, compute the 16 row dot-products (16 lanes x 16
// cols each, bank-rotated), butterfly-reduce, publish stamped R words into
// g_R. Runs ~64 steps ahead of the chain's consumption by construction.
// ---------------------------------------------------------------------------
__device__ void rhelper_body(
    float* smem, int hb, const float* __restrict__ W_ih)
{
    float (*hbuf)[256] = (float(*)[256])smem;   // double buffer
    const int tid = threadIdx.x;
    const int cl  = tid & 15;        // col block (16 cols)
    const int r16 = tid >> 4;        // row within this block's 16
    const int j   = hb * 16 + r16;   // gate row 0..1023

    // rotated weights: w[c] pairs with hbuf[cl*16 + ((c+cl)&15)]
    float w[16];
    const float* wrow = &W_ih[(size_t)j * 1280 + 1024];
#pragma unroll
    for (int c = 0; c < 16; c++) w[c] = wrow[cl * 16 + ((c + cl) & 15)];

    for (int s = 64; s < NSTEPS; s++) {
        const int par = s & 1;
        // poll h[s-64][tid] (stamped; init pattern has LSBs==2)
        const unsigned* p = &g_Hs[(size_t)(s - 64) * 256 + tid];
        unsigned u = ld_rlx32g(p);
        while ((u & 3u) == 2u) u = ld_rlx32g(p);
        hbuf[par][tid] = __uint_as_float(u);
        __syncthreads();   // one bar/step; double buffer makes reuse safe

        float a = 0.f;
        const float* hv = hbuf[par];
#pragma unroll
        for (int c = 0; c < 16; c++)
            a = fmaf(w[c], hv[cl * 16 + ((c + cl) & 15)], a);
#pragma unroll
        for (int off = 1; off < 16; off <<= 1)
            a += __shfl_xor_sync(0xffffffffu, a, off);

        if (cl == 0) {
            const unsigned rv = (__float_as_uint(a) & ~3u) | (unsigned)par;
            st_rlx32g(&g_R[(size_t)s * 1024 + j], rv);
        }
    }
}

// ---------------------------------------------------------------------------
// Chain body (R14/R15-proven, minus the out_prev phase): ONE cluster of 16
// CTAs x 256 threads, no per-step barrier. CTA k owns h-indices 16k..16k+15;
// half-warp g2 of warp w owns jj = 16k+2w+g2; lane cg handles h cols
// [16cg,16cg+16) (32 FFMA2, packed register weights — out_prev now comes
// precomputed from g_R). Pair word written as TWO independent stamped 32-bit
// cluster stores; consumers read ld.relaxed.cluster.b64 and stamp-check
// both halves. R words are stamped and checked just before the gates.
// ---------------------------------------------------------------------------
__device__ void chain_body(
    unsigned long long* mail, int k,
    const float* __restrict__ W_ih, const float* __restrict__ W_hh)
{
    const int tid  = threadIdx.x;
    const int warp = tid >> 5;
    const int lane = tid & 31;
    const int g2   = lane >> 4;
    const int cg   = lane & 15;

    const int jj = k * 16 + 2 * warp + g2;  // owned h-index

    // Register-resident packed W_hh weights: 4 gate rows x 8 col-pairs
    unsigned long long wh[4][8];
#pragma unroll
    for (int r = 0; r < 4; r++) {
        const float* whrow = &W_hh[(size_t)(jj + 256 * r) * 256];
#pragma unroll
        for (int c = 0; c < 8; c++) {
            const int col = cg * 16 + 2 * c;
            wh[r][c] = pk2(whrow[col], whrow[col + 1]);
        }
    }

    // init mailbox: slot x gets stamp (x&3)^1 in BOTH 32-bit halves
    for (int x = 0; x < MAIL_DEPTH; x++) {
        const unsigned long long iw =
            (unsigned long long)((x & 3) ^ 1) * 0x100000001ull;
        for (int i = tid; i < MAIL_SLOT; i += 256) mail[x * MAIL_SLOT + i] = iw;
    }

    const unsigned mail_base = smem_u32(mail);
    const unsigned rd_off    = (unsigned)(9 * cg) * 8u;   // my 8-pair group
    const unsigned push_base =
        mapa_rank(mail_base + (unsigned)((9 * k + warp) * 8 + 4 * g2),
                  (unsigned)cg);

    float c_state = 0.f;   // replicated per lane (bit-identical by construction)

    __syncthreads();
    asm volatile("barrier.cluster.arrive.aligned;" ::: "memory");
    asm volatile("barrier.cluster.wait.aligned;" ::: "memory");

    int m = 0;  // s % 67
    for (int s = 0; s < NSTEPS; s++) {
        // G gating (once per 64 steps) + G prefetch + stamped R prefetch
        if ((s & 63) == 0) {
            while (ld_acq32(&g_gdone[s >> 6]) < 16u) { }
        }
        float gpre[4];
        unsigned ru[4];
        {
            const size_t gb = (size_t)s * 1024 + jj;
#pragma unroll
            for (int r = 0; r < 4; r++) gpre[r] = __ldcg(&g_G[gb + 256 * r]);
            if (s >= 64) {
#pragma unroll
                for (int r = 0; r < 4; r++)
                    ru[r] = ld_rlx32g(&g_R[gb + 256 * r]);
            }
        }

        unsigned long long acc[4] = {0ull, 0ull, 0ull, 0ull};

        // ---- poll h[s-1]: 8 b64 words, BOTH halves stamp-checked
        if (s > 0) {
            const int h_slot = (m == 0) ? MAIL_DEPTH - 1 : m - 1;
            const unsigned ha = mail_base + (unsigned)(h_slot * MAIL_SLOT) * 8u + rd_off;
            const unsigned long long stamp2 =
                (unsigned long long)((s - 1) & 3) * 0x100000001ull;
            unsigned long long v[8];
            for (;;) {
                unsigned long long diff = 0ull;
#pragma unroll
                for (int c = 0; c < 8; c++) {
                    v[c] = ld_clu64(ha + c * 8);
                    diff |= (v[c] ^ stamp2);
                }
                if ((diff & 0x0000000300000003ull) == 0ull) break;
            }
#pragma unroll
            for (int c = 0; c < 8; c++) {
#pragma unroll
                for (int r = 0; r < 4; r++) acc[r] = ffma2(wh[r][c], v[c], acc[r]);
            }
        }

        // butterfly reduce over the 16 col-groups: ALL lanes get the sums
        float g4[4];
#pragma unroll
        for (int r = 0; r < 4; r++) {
            float lo, hi2;
            upk2(acc[r], lo, hi2);
            g4[r] = lo + hi2;
        }
#pragma unroll
        for (int off = 1; off < 16; off <<= 1) {
#pragma unroll
            for (int r = 0; r < 4; r++)
                g4[r] += __shfl_xor_sync(0xffffffffu, g4[r], off);
        }

        // R stamp check (loads issued at step top; ready ~64 steps early)
        if (s >= 64) {
            const size_t gb = (size_t)s * 1024 + jj;
            for (;;) {
                bool ok = true;
#pragma unroll
                for (int r = 0; r < 4; r++) ok &= ((ru[r] & 3u) != 2u);
                if (ok) break;
#pragma unroll
                for (int r = 0; r < 4; r++) ru[r] = ld_rlx32g(&g_R[gb + 256 * r]);
            }
#pragma unroll
            for (int r = 0; r < 4; r++) gpre[r] += __uint_as_float(ru[r]);
        }

        // gates: redundant across the half-warp, c_state replicated
        const float iv = fast_sigmoid(g4[0] + gpre[0]);
        const float fv = fast_sigmoid(g4[1] + gpre[1]);
        const float gv = fast_tanh  (g4[2] + gpre[2]);
        const float ov = fast_sigmoid(g4[3] + gpre[3]);
        c_state = fv * c_state + iv * gv;
        const float hv = ov * fast_tanh(c_state);

        // push FIRST: every lane stores its jj's stamped 32-bit half to rank cg
        const unsigned pv = (__float_as_uint(hv) & ~3u) | (unsigned)(s & 3);
        st_clu32(push_base + (unsigned)(m * MAIL_SLOT) * 8u, pv);

        // stamped mirror (helpers + fc consume this), off the critical path
        if (cg == 0) {
            const unsigned hw = (__float_as_uint(hv) & ~3u) | (unsigned)(s & 1);
            st_rlx32g(&g_Hs[(size_t)s * 256 + jj], hw);
        }

        m = (m + 1 == MAIL_DEPTH) ? 0 : m + 1;
    }

    asm volatile("barrier.cluster.arrive.aligned;" ::: "memory");
    asm volatile("barrier.cluster.wait.aligned;" ::: "memory");
}

// ---------------------------------------------------------------------------
// FC body (overlapped, R15-proven): 8 steps/block, per-word stamped polling
// with nanosleep backoff.
// ---------------------------------------------------------------------------
__device__ void fc_body(
    float* hrow, int fcb,
    const float* __restrict__ W_fc, const float* __restrict__ b_fc,
    float* __restrict__ out)
{
    const int tid = threadIdx.x;
    const int s0  = fcb * 8;

#pragma unroll
    for (int i = 0; i < 8; i++) {
        const unsigned* p = &g_Hs[(size_t)(s0 + i) * 256 + tid];
        unsigned u = ld_rlx32g(p);
        while ((u & 3u) == 2u) {
            __nanosleep(1000);
            u = ld_rlx32g(p);
        }
        hrow[i * 256 + tid] = __uint_as_float(u);
    }
    __syncthreads();

    const int sub = tid >> 7;
    const int l   = tid & 127;
    float acc[4];
    const float bias = b_fc[l];
#pragma unroll
    for (int q = 0; q < 4; q++) acc[q] = bias;

    const float* wr = &W_fc[(size_t)l * 256];
    const float* h0 = &hrow[(sub * 4) * 256];
#pragma unroll 4
    for (int j = 0; j < 256; j++) {
        const float wv = wr[j];
#pragma unroll
        for (int q = 0; q < 4; q++)
            acc[q] = fmaf(wv, h0[q * 256 + j], acc[q]);
    }

#pragma unroll
    for (int q = 0; q < 4; q++) {
        const int s = s0 + sub * 4 + q;
        const int t = s >> 6, b = s & 63;
        out[((size_t)b << 14) + (size_t)t * 128 + l] = acc[q];
    }
}

// ---------------------------------------------------------------------------
// Fused kernel: [0,16) chain cluster; [16,80) R-helpers (resident early);
// [80,2128) GEMM tiles; [2128,3152) fc blocks.
// ---------------------------------------------------------------------------
__global__ void __launch_bounds__(256) fused_kernel(
    const float* __restrict__ x, const float* __restrict__ hi,
    const float* __restrict__ W_ih, const float* __restrict__ W_hh,
    const float* __restrict__ b_ih, const float* __restrict__ b_hh,
    const float* __restrict__ W_fc, const float* __restrict__ b_fc,
    float* __restrict__ out)
{
    extern __shared__ unsigned long long dynsmem[];
    const int b = blockIdx.x;
    if (b < CHAIN_CTAS) {
        chain_body(dynsmem, b, W_ih, W_hh);
    } else if (b < CHAIN_CTAS + RHELP_BLOCKS) {
        rhelper_body((float*)dynsmem, b - CHAIN_CTAS, W_ih);
    } else if (b < CHAIN_CTAS + RHELP_BLOCKS + GEMM_BLOCKS) {
        gemm_body((float*)dynsmem, b - (CHAIN_CTAS + RHELP_BLOCKS),
                  x, hi, W_ih, b_ih, b_hh);
    } else {
        fc_body((float*)dynsmem, b - (CHAIN_CTAS + RHELP_BLOCKS + GEMM_BLOCKS),
                W_fc, b_fc, out);
    }
}

// ---------------------------------------------------------------------------
extern "C" void kernel_launch(void* const* d_in, const int* in_sizes, int n_in,
                              void* d_out, int out_size)
{
    const float* x    = (const float*)d_in[0];
    const float* hi   = (const float*)d_in[1];
    const float* W_ih = (const float*)d_in[2];
    const float* W_hh = (const float*)d_in[3];
    const float* b_ih = (const float*)d_in[4];
    const float* b_hh = (const float*)d_in[5];
    const float* W_fc = (const float*)d_in[6];
    const float* b_fc = (const float*)d_in[7];
    float* out = (float*)d_out;

    // reset counters + stamped buffers (0xAA -> LSBs == 2) each replay
    void* gp = nullptr;
    cudaGetSymbolAddress(&gp, g_gdone);
    cudaMemsetAsync(gp, 0, 128 * sizeof(unsigned));
    void* hp = nullptr;
    cudaGetSymbolAddress(&hp, g_Hs);
    cudaMemsetAsync(hp, 0xAA, 8192u * 256u * sizeof(unsigned));
    void* rp = nullptr;
    cudaGetSymbolAddress(&rp, g_R);
    cudaMemsetAsync(rp, 0xAA, 8192u * 1024u * sizeof(unsigned));

    const int smem_bytes = MAIL_DEPTH * MAIL_SLOT * sizeof(unsigned long long); // 77184
    cudaFuncSetAttribute(fused_kernel,
                         cudaFuncAttributeMaxDynamicSharedMemorySize, smem_bytes);
    cudaFuncSetAttribute(fused_kernel,
                         cudaFuncAttributeNonPortableClusterSizeAllowed, 1);

    cudaLaunchConfig_t cfg = {};
    cfg.gridDim  = dim3(CHAIN_CTAS + RHELP_BLOCKS + GEMM_BLOCKS + FC_BLOCKS, 1, 1);
    cfg.blockDim = dim3(256, 1, 1);   // 3152 = 197 * 16
    cfg.dynamicSmemBytes = smem_bytes;
    cudaLaunchAttribute attrs[1];
    attrs[0].id = cudaLaunchAttributeClusterDimension;
    attrs[0].val.clusterDim.x = 16;
    attrs[0].val.clusterDim.y = 1;
    attrs[0].val.clusterDim.z = 1;
    cfg.attrs = attrs;
    cfg.numAttrs = 1;
    cudaLaunchKernelEx(&cfg, fused_kernel, x, hi, W_ih, W_hh, b_ih, b_hh,
                       W_fc, b_fc, out);
}